// round 15
// baseline (speedup 1.0000x reference)
#include <cuda_runtime.h>
#include <cuda_bf16.h>
#include <math.h>
#include <stdint.h>

#define F_IN 512
#define HID  256
#define NCLS 40
#define MAXN 100000
#define MAXE 1600000
#define NPB  16   // nodes per block in fused agg1+gemm2

// ---- scratch ----
__device__ float g_h1  [(size_t)MAXN * HID];
__device__ float g_h2  [(size_t)MAXN * NCLS];
__device__ float g_dinv[MAXN];
__device__ int   g_cnt [MAXN];
__device__ int   g_rowstart[MAXN + 1];
__device__ int   g_cursor[MAXN];
__device__ int   g_se[MAXE];
__device__ float g_ce[MAXE];
__device__ int   g_bsum[128];
__device__ __nv_bfloat16 g_w1hi[(size_t)HID * F_IN];   // [n][k] transposed
__device__ __nv_bfloat16 g_w1lo[(size_t)HID * F_IN];

#define MMA_BF16(c, a, b) \
    asm volatile("mma.sync.aligned.m16n8k16.row.col.f32.bf16.bf16.f32 " \
                 "{%0,%1,%2,%3}, {%4,%5,%6,%7}, {%8,%9}, {%0,%1,%2,%3};" \
                 : "+f"((c)[0]), "+f"((c)[1]), "+f"((c)[2]), "+f"((c)[3]) \
                 : "r"((a)[0]), "r"((a)[1]), "r"((a)[2]), "r"((a)[3]), \
                   "r"((b)[0]), "r"((b)[1]))

#define LDSM4(r0, r1, r2, r3, addr) \
    asm volatile("ldmatrix.sync.aligned.m8n8.x4.shared.b16 {%0,%1,%2,%3}, [%4];" \
                 : "=r"(r0), "=r"(r1), "=r"(r2), "=r"(r3) : "r"(addr))

__device__ __forceinline__ uint32_t pack2(__nv_bfloat16 a, __nv_bfloat16 b) {
    return (uint32_t)__bfloat16_as_ushort(a) | ((uint32_t)__bfloat16_as_ushort(b) << 16);
}

// ---------------- prep ----------------
__global__ void k_split_zero(const float* __restrict__ W1) {
    int i = blockIdx.x * 256 + threadIdx.x;
    if (i < MAXN) g_cnt[i] = 0;
    if (i < F_IN * HID) {
        int k = i >> 8, n = i & 255;
        float w = W1[(size_t)k * HID + n];
        __nv_bfloat16 hi = __float2bfloat16_rn(w);
        __nv_bfloat16 lo = __float2bfloat16_rn(w - __bfloat162float(hi));
        g_w1hi[(size_t)n * F_IN + k] = hi;
        g_w1lo[(size_t)n * F_IN + k] = lo;
    }
}

__global__ void k_count(const int* __restrict__ ei, int E) {
    int e = blockIdx.x * 256 + threadIdx.x;
    if (e >= E) return;
    atomicAdd(&g_cnt[ei[E + e]], 1);
}

__global__ void k_scan1(int M) {
    __shared__ int sd[1024];
    int t = threadIdx.x, b = blockIdx.x;
    int i = b * 1024 + t;
    int v = (i < M) ? g_cnt[i] : 0;
    sd[t] = v;
    __syncthreads();
    for (int off = 1; off < 1024; off <<= 1) {
        int x = (t >= off) ? sd[t - off] : 0;
        __syncthreads();
        sd[t] += x;
        __syncthreads();
    }
    if (i < M) g_rowstart[i] = sd[t] - v;
    if (t == 1023) g_bsum[b] = sd[1023];
}

__global__ void k_scan2(int nb) {
    __shared__ int sd[128];
    int t = threadIdx.x;
    int v = (t < nb) ? g_bsum[t] : 0;
    sd[t] = v;
    __syncthreads();
    for (int off = 1; off < 128; off <<= 1) {
        int x = (t >= off) ? sd[t - off] : 0;
        __syncthreads();
        sd[t] += x;
        __syncthreads();
    }
    if (t < nb) g_bsum[t] = sd[t] - v;
}

__global__ void k_scan3(int M, int E) {
    int i = blockIdx.x * 256 + threadIdx.x;
    if (i >= M) return;
    int rs = g_rowstart[i] + g_bsum[i >> 10];
    g_rowstart[i] = rs;
    g_cursor[i] = rs;
    g_dinv[i] = rsqrtf((float)g_cnt[i] + 1.0f);
    if (i == 0) g_rowstart[M] = E;
}

__global__ void k_bucket(const int* __restrict__ ei, int E) {
    int e = blockIdx.x * 256 + threadIdx.x;
    if (e >= E) return;
    int s = ei[e], d = ei[E + e];
    int pos = atomicAdd(&g_cursor[d], 1);
    g_se[pos] = s;
    g_ce[pos] = g_dinv[s] * g_dinv[d];
}

// ---------------- GEMM1: bf16x3 mma + ldmatrix, reg-capped for 2 CTA/SM ----------------
#define ASTR2 72
__global__ void __launch_bounds__(256, 2) k_gemm1(const float* __restrict__ A, int M) {
    __shared__ __nv_bfloat16 Asm[128 * ASTR2];
    __shared__ __nv_bfloat16 Bsm[128 * ASTR2];
    int tid = threadIdx.x, lane = tid & 31, wid = tid >> 5;
    int bm = blockIdx.y * 128, bn = blockIdx.x * 128;
    int m0 = (wid & 1) * 64, n0 = (wid >> 1) * 32;

    uint32_t aBase0 = (uint32_t)__cvta_generic_to_shared(Asm) +
                      (uint32_t)(((m0 + (lane & 15)) * ASTR2 + (lane >> 4) * 8) * 2);
    uint32_t bBase0 = (uint32_t)__cvta_generic_to_shared(Bsm) +
                      (uint32_t)(((n0 + (lane & 7)) * ASTR2 +
                                  ((lane >> 3) & 1) * 8 + (lane >> 4) * 32) * 2);

    float c[4][4][4];
#pragma unroll
    for (int i = 0; i < 4; i++)
#pragma unroll
        for (int j = 0; j < 4; j++)
#pragma unroll
            for (int r = 0; r < 4; r++) c[i][j][r] = 0.0f;

    for (int s = 0; s < F_IN / 32; s++) {
        int k0 = s * 32;
#pragma unroll
        for (int i = 0; i < 4; i++) {
            int ch = tid + i * 256;
            int m = ch >> 3, k4 = ch & 7;
            float4 a = make_float4(0.f, 0.f, 0.f, 0.f);
            if (bm + m < M)
                a = *(const float4*)(A + (size_t)(bm + m) * F_IN + k0 + k4 * 4);
            __nv_bfloat16 hx = __float2bfloat16_rn(a.x), hy = __float2bfloat16_rn(a.y);
            __nv_bfloat16 hz = __float2bfloat16_rn(a.z), hw = __float2bfloat16_rn(a.w);
            __nv_bfloat16 lx = __float2bfloat16_rn(a.x - __bfloat162float(hx));
            __nv_bfloat16 ly = __float2bfloat16_rn(a.y - __bfloat162float(hy));
            __nv_bfloat16 lz = __float2bfloat16_rn(a.z - __bfloat162float(hz));
            __nv_bfloat16 lw = __float2bfloat16_rn(a.w - __bfloat162float(hw));
            *(uint2*)&Asm[m * ASTR2 + k4 * 4]      = make_uint2(pack2(hx, hy), pack2(hz, hw));
            *(uint2*)&Asm[m * ASTR2 + 32 + k4 * 4] = make_uint2(pack2(lx, ly), pack2(lz, lw));
        }
#pragma unroll
        for (int i = 0; i < 4; i++) {
            int ch = tid + i * 256;
            int n = ch >> 3, q = ch & 7;
            if (q < 4)
                *(uint4*)&Bsm[n * ASTR2 + q * 8] =
                    *(const uint4*)(g_w1hi + (size_t)(bn + n) * F_IN + k0 + q * 8);
            else
                *(uint4*)&Bsm[n * ASTR2 + 32 + (q - 4) * 8] =
                    *(const uint4*)(g_w1lo + (size_t)(bn + n) * F_IN + k0 + (q - 4) * 8);
        }
        __syncthreads();

#pragma unroll
        for (int kk = 0; kk < 32; kk += 16) {
            uint32_t ah[4][4], al[4][4], bh[4][2], bl[4][2];
#pragma unroll
            for (int tm = 0; tm < 4; tm++) {
                uint32_t aa = aBase0 + (uint32_t)(tm * 16 * ASTR2 * 2 + kk * 2);
                LDSM4(ah[tm][0], ah[tm][1], ah[tm][2], ah[tm][3], aa);
                LDSM4(al[tm][0], al[tm][1], al[tm][2], al[tm][3], aa + 64);
            }
#pragma unroll
            for (int tn = 0; tn < 4; tn++) {
                uint32_t bb = bBase0 + (uint32_t)(tn * 8 * ASTR2 * 2 + kk * 2);
                LDSM4(bh[tn][0], bh[tn][1], bl[tn][0], bl[tn][1], bb);
            }
#pragma unroll
            for (int tm = 0; tm < 4; tm++)
#pragma unroll
                for (int tn = 0; tn < 4; tn++) {
                    MMA_BF16(c[tm][tn], ah[tm], bh[tn]);
                    MMA_BF16(c[tm][tn], ah[tm], bl[tn]);
                    MMA_BF16(c[tm][tn], al[tm], bh[tn]);
                }
        }
        __syncthreads();
    }

#pragma unroll
    for (int tm = 0; tm < 4; tm++) {
        int row0 = bm + m0 + tm * 16 + (lane >> 2);
#pragma unroll
        for (int h = 0; h < 2; h++) {
            int row = row0 + h * 8;
            if (row >= M) continue;
#pragma unroll
            for (int tn = 0; tn < 4; tn++) {
                int col = bn + n0 + tn * 8 + (lane & 3) * 2;
                *(float2*)(g_h1 + (size_t)row * HID + col) =
                    make_float2(c[tm][tn][h * 2 + 0], c[tm][tn][h * 2 + 1]);
            }
        }
    }
}

// ---------------- fused agg1 + bias/relu + GEMM2: block per NPB nodes ----------------
// gather stays identical to k_agg1; per-node 256-vector never leaves the block.
__global__ void __launch_bounds__(256) k_agg1gemm2(const float* __restrict__ W2,
                                                   const float* __restrict__ b1, int M) {
    __shared__ float W2sT[NCLS][HID];   // transposed: row j = W2[:,j], lanes stride-1
    __shared__ float xs[HID];
    int tid = threadIdx.x, lane = tid & 31, wid = tid >> 5;

    for (int idx = tid; idx < HID * NCLS; idx += 256) {
        int t = idx / NCLS, j = idx % NCLS;
        W2sT[j][t] = W2[idx];
    }
    float bias = b1[tid];
    __syncthreads();

    int n0 = blockIdx.x * NPB;
    for (int nn = 0; nn < NPB; nn++) {
        int n = n0 + nn;
        if (n >= M) break;
        int st = g_rowstart[n], en = g_rowstart[n + 1];
        float dv = g_dinv[n];
        float acc = g_h1[(size_t)n * HID + tid] * (dv * dv);
        int e = st;
        for (; e + 3 < en; e += 4) {
            int s0 = g_se[e], s1 = g_se[e + 1], s2 = g_se[e + 2], s3 = g_se[e + 3];
            float c0 = g_ce[e], c1 = g_ce[e + 1], c2 = g_ce[e + 2], c3 = g_ce[e + 3];
            float v0 = __ldg(g_h1 + (size_t)s0 * HID + tid);
            float v1 = __ldg(g_h1 + (size_t)s1 * HID + tid);
            float v2 = __ldg(g_h1 + (size_t)s2 * HID + tid);
            float v3 = __ldg(g_h1 + (size_t)s3 * HID + tid);
            acc += v0 * c0 + v1 * c1 + v2 * c2 + v3 * c3;
        }
        for (; e < en; e++)
            acc += __ldg(g_h1 + (size_t)g_se[e] * HID + tid) * g_ce[e];

        xs[tid] = fmaxf(acc + bias, 0.0f);
        __syncthreads();

        // GEMV: warp wid -> outputs j = wid*5 .. wid*5+4
#pragma unroll
        for (int jj = 0; jj < 5; jj++) {
            int j = wid * 5 + jj;
            float p = 0.0f;
#pragma unroll
            for (int i = 0; i < 8; i++) {
                int t = lane + 32 * i;
                p += xs[t] * W2sT[j][t];
            }
#pragma unroll
            for (int o = 16; o; o >>= 1) p += __shfl_xor_sync(0xffffffffu, p, o);
            if (lane == 0) g_h2[(size_t)n * NCLS + j] = p;
        }
        __syncthreads();   // xs reused next node
    }
}

// ---------------- fused agg layer 2 + bias + log_softmax/softmax ----------------
__global__ void __launch_bounds__(256) k_agg2soft(const float* __restrict__ b2,
                                                  float* __restrict__ out,
                                                  int M, int write_soft) {
    int warp = threadIdx.x >> 5, lane = threadIdx.x & 31;
    int n = blockIdx.x * 8 + warp;
    if (n >= M) return;
    int st = g_rowstart[n], en = g_rowstart[n + 1];
    float dv = g_dinv[n];
    float d2 = dv * dv;
    bool has1 = lane < (NCLS - 32);
    const float* hn = g_h2 + (size_t)n * NCLS;
    float a0 = hn[lane] * d2;
    float a1 = has1 ? hn[32 + lane] * d2 : 0.0f;
    for (int e = st; e < en; e++) {
        int s = g_se[e];
        float cc = g_ce[e];
        const float* hs = g_h2 + (size_t)s * NCLS;
        a0 += hs[lane] * cc;
        if (has1) a1 += hs[32 + lane] * cc;
    }
    float v0 = a0 + b2[lane];
    float v1 = has1 ? (a1 + b2[32 + lane]) : -INFINITY;
    float m = fmaxf(v0, v1);
#pragma unroll
    for (int o = 16; o; o >>= 1) m = fmaxf(m, __shfl_xor_sync(0xffffffffu, m, o));
    float s = expf(v0 - m) + (has1 ? expf(v1 - m) : 0.0f);
#pragma unroll
    for (int o = 16; o; o >>= 1) s += __shfl_xor_sync(0xffffffffu, s, o);
    float lse = m + logf(s);
    float l0 = v0 - lse;
    out[(size_t)n * NCLS + lane] = l0;
    if (write_soft) out[(size_t)M * NCLS + (size_t)n * NCLS + lane] = expf(l0);
    if (has1) {
        float l1 = v1 - lse;
        out[(size_t)n * NCLS + lane + 32] = l1;
        if (write_soft) out[(size_t)M * NCLS + (size_t)n * NCLS + lane + 32] = expf(l1);
    }
}

extern "C" void kernel_launch(void* const* d_in, const int* in_sizes, int n_in,
                              void* d_out, int out_size) {
    const float* features = (const float*)d_in[0];
    const float* W1       = (const float*)d_in[1];
    const float* b1       = (const float*)d_in[2];
    const float* W2       = (const float*)d_in[3];
    const float* b2       = (const float*)d_in[4];
    const int*   ei       = (const int*)d_in[5];

    int M = in_sizes[0] / F_IN;
    int E = in_sizes[5] / 2;
    float* out = (float*)d_out;
    int write_soft = (out_size >= 2 * M * NCLS) ? 1 : 0;
    int nb = (M + 1023) / 1024;

    static cudaStream_t s2 = 0;
    static cudaEvent_t evFork = 0, evJoin = 0;
    if (!s2) {
        cudaStreamCreateWithFlags(&s2, cudaStreamNonBlocking);
        cudaEventCreateWithFlags(&evFork, cudaEventDisableTiming);
        cudaEventCreateWithFlags(&evJoin, cudaEventDisableTiming);
    }

    k_split_zero<<<(F_IN * HID + 255) / 256, 256>>>(W1);       // launch 1 (main)

    cudaEventRecord(evFork, 0);
    cudaStreamWaitEvent(s2, evFork, 0);

    k_count<<<(E + 255) / 256, 256, 0, s2>>>(ei, E);           // launch 2 (s2)
    k_scan1<<<nb, 1024, 0, s2>>>(M);                           // launch 3 (s2)

    dim3 g1(HID / 128, (M + 127) / 128);
    k_gemm1<<<g1, 256>>>(features, M);                         // launch 4 (main) <- profiled

    k_scan2<<<1, 128, 0, s2>>>(nb);                            // launch 5 (s2)
    k_scan3<<<(M + 255) / 256, 256, 0, s2>>>(M, E);            // launch 6 (s2)
    k_bucket<<<(E + 255) / 256, 256, 0, s2>>>(ei, E);          // launch 7 (s2)

    cudaEventRecord(evJoin, s2);
    cudaStreamWaitEvent(0, evJoin, 0);

    k_agg1gemm2<<<(M + NPB - 1) / NPB, 256>>>(W2, b1, M);      // launch 8
    k_agg2soft<<<(M + 7) / 8, 256>>>(b2, out, M, write_soft);  // launch 9
}

// round 16
// speedup vs baseline: 1.3840x; 1.3840x over previous
#include <cuda_runtime.h>
#include <cuda_bf16.h>
#include <math.h>
#include <stdint.h>

#define F_IN 512
#define HID  256
#define NCLS 40
#define MAXN 100000
#define MAXE 1600000

// ---- scratch ----
__device__ float g_h1  [(size_t)MAXN * HID];
__device__ float g_agg1[(size_t)MAXN * HID];
__device__ float g_h2  [(size_t)MAXN * NCLS];
__device__ float g_dinv[MAXN];
__device__ int   g_cnt [MAXN];
__device__ int   g_rowstart[MAXN + 1];
__device__ int   g_cursor[MAXN];
__device__ int   g_se[MAXE];
__device__ float g_ce[MAXE];
__device__ int   g_bsum[128];
__device__ __nv_bfloat16 g_w1hi[(size_t)HID * F_IN];   // [n][k] transposed
__device__ __nv_bfloat16 g_w1lo[(size_t)HID * F_IN];

#define MMA_BF16(c, a, b) \
    asm volatile("mma.sync.aligned.m16n8k16.row.col.f32.bf16.bf16.f32 " \
                 "{%0,%1,%2,%3}, {%4,%5,%6,%7}, {%8,%9}, {%0,%1,%2,%3};" \
                 : "+f"((c)[0]), "+f"((c)[1]), "+f"((c)[2]), "+f"((c)[3]) \
                 : "r"((a)[0]), "r"((a)[1]), "r"((a)[2]), "r"((a)[3]), \
                   "r"((b)[0]), "r"((b)[1]))

#define LDSM4(r0, r1, r2, r3, addr) \
    asm volatile("ldmatrix.sync.aligned.m8n8.x4.shared.b16 {%0,%1,%2,%3}, [%4];" \
                 : "=r"(r0), "=r"(r1), "=r"(r2), "=r"(r3) : "r"(addr))

__device__ __forceinline__ uint32_t pack2(__nv_bfloat16 a, __nv_bfloat16 b) {
    return (uint32_t)__bfloat16_as_ushort(a) | ((uint32_t)__bfloat16_as_ushort(b) << 16);
}

// ---------------- prep ----------------
__global__ void k_split_zero(const float* __restrict__ W1) {
    int i = blockIdx.x * 256 + threadIdx.x;
    if (i < MAXN) g_cnt[i] = 0;
    if (i < F_IN * HID) {
        int k = i >> 8, n = i & 255;
        float w = W1[(size_t)k * HID + n];
        __nv_bfloat16 hi = __float2bfloat16_rn(w);
        __nv_bfloat16 lo = __float2bfloat16_rn(w - __bfloat162float(hi));
        g_w1hi[(size_t)n * F_IN + k] = hi;
        g_w1lo[(size_t)n * F_IN + k] = lo;
    }
}

__global__ void k_count(const int* __restrict__ ei, int E) {
    int e = blockIdx.x * 256 + threadIdx.x;
    if (e >= E) return;
    atomicAdd(&g_cnt[ei[E + e]], 1);
}

__global__ void k_scan1(int M) {
    __shared__ int sd[1024];
    int t = threadIdx.x, b = blockIdx.x;
    int i = b * 1024 + t;
    int v = (i < M) ? g_cnt[i] : 0;
    sd[t] = v;
    __syncthreads();
    for (int off = 1; off < 1024; off <<= 1) {
        int x = (t >= off) ? sd[t - off] : 0;
        __syncthreads();
        sd[t] += x;
        __syncthreads();
    }
    if (i < M) g_rowstart[i] = sd[t] - v;
    if (t == 1023) g_bsum[b] = sd[1023];
}

__global__ void k_scan2(int nb) {
    __shared__ int sd[128];
    int t = threadIdx.x;
    int v = (t < nb) ? g_bsum[t] : 0;
    sd[t] = v;
    __syncthreads();
    for (int off = 1; off < 128; off <<= 1) {
        int x = (t >= off) ? sd[t - off] : 0;
        __syncthreads();
        sd[t] += x;
        __syncthreads();
    }
    if (t < nb) g_bsum[t] = sd[t] - v;
}

__global__ void k_scan3(int M, int E) {
    int i = blockIdx.x * 256 + threadIdx.x;
    if (i >= M) return;
    int rs = g_rowstart[i] + g_bsum[i >> 10];
    g_rowstart[i] = rs;
    g_cursor[i] = rs;
    g_dinv[i] = rsqrtf((float)g_cnt[i] + 1.0f);
    if (i == 0) g_rowstart[M] = E;
}

__global__ void k_bucket(const int* __restrict__ ei, int E) {
    int e = blockIdx.x * 256 + threadIdx.x;
    if (e >= E) return;
    int s = ei[e], d = ei[E + e];
    int pos = atomicAdd(&g_cursor[d], 1);
    g_se[pos] = s;
    g_ce[pos] = g_dinv[s] * g_dinv[d];
}

// ---------------- GEMM1: bf16x3 mma + ldmatrix, reg-capped for 2 CTA/SM ----------------
#define ASTR2 72
__global__ void __launch_bounds__(256, 2) k_gemm1(const float* __restrict__ A, int M) {
    __shared__ __nv_bfloat16 Asm[128 * ASTR2];
    __shared__ __nv_bfloat16 Bsm[128 * ASTR2];
    int tid = threadIdx.x, lane = tid & 31, wid = tid >> 5;
    int bm = blockIdx.y * 128, bn = blockIdx.x * 128;
    int m0 = (wid & 1) * 64, n0 = (wid >> 1) * 32;

    uint32_t aBase0 = (uint32_t)__cvta_generic_to_shared(Asm) +
                      (uint32_t)(((m0 + (lane & 15)) * ASTR2 + (lane >> 4) * 8) * 2);
    uint32_t bBase0 = (uint32_t)__cvta_generic_to_shared(Bsm) +
                      (uint32_t)(((n0 + (lane & 7)) * ASTR2 +
                                  ((lane >> 3) & 1) * 8 + (lane >> 4) * 32) * 2);

    float c[4][4][4];
#pragma unroll
    for (int i = 0; i < 4; i++)
#pragma unroll
        for (int j = 0; j < 4; j++)
#pragma unroll
            for (int r = 0; r < 4; r++) c[i][j][r] = 0.0f;

    for (int s = 0; s < F_IN / 32; s++) {
        int k0 = s * 32;
#pragma unroll
        for (int i = 0; i < 4; i++) {
            int ch = tid + i * 256;
            int m = ch >> 3, k4 = ch & 7;
            float4 a = make_float4(0.f, 0.f, 0.f, 0.f);
            if (bm + m < M)
                a = *(const float4*)(A + (size_t)(bm + m) * F_IN + k0 + k4 * 4);
            __nv_bfloat16 hx = __float2bfloat16_rn(a.x), hy = __float2bfloat16_rn(a.y);
            __nv_bfloat16 hz = __float2bfloat16_rn(a.z), hw = __float2bfloat16_rn(a.w);
            __nv_bfloat16 lx = __float2bfloat16_rn(a.x - __bfloat162float(hx));
            __nv_bfloat16 ly = __float2bfloat16_rn(a.y - __bfloat162float(hy));
            __nv_bfloat16 lz = __float2bfloat16_rn(a.z - __bfloat162float(hz));
            __nv_bfloat16 lw = __float2bfloat16_rn(a.w - __bfloat162float(hw));
            *(uint2*)&Asm[m * ASTR2 + k4 * 4]      = make_uint2(pack2(hx, hy), pack2(hz, hw));
            *(uint2*)&Asm[m * ASTR2 + 32 + k4 * 4] = make_uint2(pack2(lx, ly), pack2(lz, lw));
        }
#pragma unroll
        for (int i = 0; i < 4; i++) {
            int ch = tid + i * 256;
            int n = ch >> 3, q = ch & 7;
            if (q < 4)
                *(uint4*)&Bsm[n * ASTR2 + q * 8] =
                    *(const uint4*)(g_w1hi + (size_t)(bn + n) * F_IN + k0 + q * 8);
            else
                *(uint4*)&Bsm[n * ASTR2 + 32 + (q - 4) * 8] =
                    *(const uint4*)(g_w1lo + (size_t)(bn + n) * F_IN + k0 + (q - 4) * 8);
        }
        __syncthreads();

#pragma unroll
        for (int kk = 0; kk < 32; kk += 16) {
            uint32_t ah[4][4], al[4][4], bh[4][2], bl[4][2];
#pragma unroll
            for (int tm = 0; tm < 4; tm++) {
                uint32_t aa = aBase0 + (uint32_t)(tm * 16 * ASTR2 * 2 + kk * 2);
                LDSM4(ah[tm][0], ah[tm][1], ah[tm][2], ah[tm][3], aa);
                LDSM4(al[tm][0], al[tm][1], al[tm][2], al[tm][3], aa + 64);
            }
#pragma unroll
            for (int tn = 0; tn < 4; tn++) {
                uint32_t bb = bBase0 + (uint32_t)(tn * 8 * ASTR2 * 2 + kk * 2);
                LDSM4(bh[tn][0], bh[tn][1], bl[tn][0], bl[tn][1], bb);
            }
#pragma unroll
            for (int tm = 0; tm < 4; tm++)
#pragma unroll
                for (int tn = 0; tn < 4; tn++) {
                    MMA_BF16(c[tm][tn], ah[tm], bh[tn]);
                    MMA_BF16(c[tm][tn], ah[tm], bl[tn]);
                    MMA_BF16(c[tm][tn], al[tm], bh[tn]);
                }
        }
        __syncthreads();
    }

#pragma unroll
    for (int tm = 0; tm < 4; tm++) {
        int row0 = bm + m0 + tm * 16 + (lane >> 2);
#pragma unroll
        for (int h = 0; h < 2; h++) {
            int row = row0 + h * 8;
            if (row >= M) continue;
#pragma unroll
            for (int tn = 0; tn < 4; tn++) {
                int col = bn + n0 + tn * 8 + (lane & 3) * 2;
                *(float2*)(g_h1 + (size_t)row * HID + col) =
                    make_float2(c[tm][tn][h * 2 + 0], c[tm][tn][h * 2 + 1]);
            }
        }
    }
}

// ---------------- agg layer 1: block per dst node, unroll 8, no atomics ----------------
__global__ void __launch_bounds__(256) k_agg1(int M) {
    int n = blockIdx.x;
    int tid = threadIdx.x;
    int st = g_rowstart[n], en = g_rowstart[n + 1];
    float dv = g_dinv[n];
    float acc = g_h1[(size_t)n * HID + tid] * (dv * dv);
    int e = st;
    for (; e + 7 < en; e += 8) {
        int   s[8];
        float cc[8], v[8];
#pragma unroll
        for (int q = 0; q < 8; q++) { s[q] = g_se[e + q]; cc[q] = g_ce[e + q]; }
#pragma unroll
        for (int q = 0; q < 8; q++) v[q] = __ldg(g_h1 + (size_t)s[q] * HID + tid);
#pragma unroll
        for (int q = 0; q < 8; q++) acc += v[q] * cc[q];
    }
    for (; e < en; e++)
        acc += __ldg(g_h1 + (size_t)g_se[e] * HID + tid) * g_ce[e];
    g_agg1[(size_t)n * HID + tid] = acc;
}

// ---------------- GEMM2 (bias+relu fused A-loader) ----------------
__global__ void __launch_bounds__(256) k_gemm2(const float* __restrict__ W2,
                                               const float* __restrict__ b1, int M) {
    __shared__ float As[32][128];
    __shared__ float Ws[32][NCLS];
    int tid = threadIdx.x;
    int tx = tid & 7, ty = tid >> 3;
    int bm = blockIdx.x * 128;

    float acc[4][5];
#pragma unroll
    for (int i = 0; i < 4; i++)
#pragma unroll
        for (int j = 0; j < 5; j++) acc[i][j] = 0.0f;

    for (int k0 = 0; k0 < HID; k0 += 32) {
#pragma unroll
        for (int i = 0; i < 4; i++) {
            int lin = tid + i * 256;
            int r = lin >> 3, c4 = lin & 7;
            int row = bm + r;
            float4 a4 = make_float4(0.f, 0.f, 0.f, 0.f);
            if (row < M) {
                a4 = *(const float4*)(g_agg1 + (size_t)row * HID + k0 + c4 * 4);
                float4 bb = *(const float4*)(b1 + k0 + c4 * 4);
                a4.x = fmaxf(a4.x + bb.x, 0.0f);
                a4.y = fmaxf(a4.y + bb.y, 0.0f);
                a4.z = fmaxf(a4.z + bb.z, 0.0f);
                a4.w = fmaxf(a4.w + bb.w, 0.0f);
            }
            As[c4 * 4 + 0][r] = a4.x;
            As[c4 * 4 + 1][r] = a4.y;
            As[c4 * 4 + 2][r] = a4.z;
            As[c4 * 4 + 3][r] = a4.w;
        }
#pragma unroll
        for (int i = 0; i < 5; i++) {
            int lin = tid + i * 256;
            int r = lin / NCLS, c = lin % NCLS;
            Ws[r][c] = W2[(size_t)(k0 + r) * NCLS + c];
        }
        __syncthreads();

#pragma unroll
        for (int kk = 0; kk < 32; kk++) {
            float4 a = *(float4*)&As[kk][ty * 4];
            float av[4] = {a.x, a.y, a.z, a.w};
            float w[5];
#pragma unroll
            for (int j = 0; j < 5; j++) w[j] = Ws[kk][tx * 5 + j];
#pragma unroll
            for (int i = 0; i < 4; i++)
#pragma unroll
                for (int j = 0; j < 5; j++)
                    acc[i][j] = fmaf(av[i], w[j], acc[i][j]);
        }
        __syncthreads();
    }

#pragma unroll
    for (int i = 0; i < 4; i++) {
        int row = bm + ty * 4 + i;
        if (row >= M) continue;
#pragma unroll
        for (int j = 0; j < 5; j++)
            g_h2[(size_t)row * NCLS + tx * 5 + j] = acc[i][j];
    }
}

// ---------------- fused agg layer 2 + bias + log_softmax/softmax ----------------
__global__ void __launch_bounds__(256) k_agg2soft(const float* __restrict__ b2,
                                                  float* __restrict__ out,
                                                  int M, int write_soft) {
    int warp = threadIdx.x >> 5, lane = threadIdx.x & 31;
    int n = blockIdx.x * 8 + warp;
    if (n >= M) return;
    int st = g_rowstart[n], en = g_rowstart[n + 1];
    float dv = g_dinv[n];
    float d2 = dv * dv;
    bool has1 = lane < (NCLS - 32);
    const float* hn = g_h2 + (size_t)n * NCLS;
    float a0 = hn[lane] * d2;
    float a1 = has1 ? hn[32 + lane] * d2 : 0.0f;
    for (int e = st; e < en; e++) {
        int s = g_se[e];
        float cc = g_ce[e];
        const float* hs = g_h2 + (size_t)s * NCLS;
        a0 += hs[lane] * cc;
        if (has1) a1 += hs[32 + lane] * cc;
    }
    float v0 = a0 + b2[lane];
    float v1 = has1 ? (a1 + b2[32 + lane]) : -INFINITY;
    float m = fmaxf(v0, v1);
#pragma unroll
    for (int o = 16; o; o >>= 1) m = fmaxf(m, __shfl_xor_sync(0xffffffffu, m, o));
    float s = expf(v0 - m) + (has1 ? expf(v1 - m) : 0.0f);
#pragma unroll
    for (int o = 16; o; o >>= 1) s += __shfl_xor_sync(0xffffffffu, s, o);
    float lse = m + logf(s);
    float l0 = v0 - lse;
    out[(size_t)n * NCLS + lane] = l0;
    if (write_soft) out[(size_t)M * NCLS + (size_t)n * NCLS + lane] = expf(l0);
    if (has1) {
        float l1 = v1 - lse;
        out[(size_t)n * NCLS + lane + 32] = l1;
        if (write_soft) out[(size_t)M * NCLS + (size_t)n * NCLS + lane + 32] = expf(l1);
    }
}

extern "C" void kernel_launch(void* const* d_in, const int* in_sizes, int n_in,
                              void* d_out, int out_size) {
    const float* features = (const float*)d_in[0];
    const float* W1       = (const float*)d_in[1];
    const float* b1       = (const float*)d_in[2];
    const float* W2       = (const float*)d_in[3];
    const float* b2       = (const float*)d_in[4];
    const int*   ei       = (const int*)d_in[5];

    int M = in_sizes[0] / F_IN;
    int E = in_sizes[5] / 2;
    float* out = (float*)d_out;
    int write_soft = (out_size >= 2 * M * NCLS) ? 1 : 0;
    int nb = (M + 1023) / 1024;

    static cudaStream_t s2 = 0;
    static cudaEvent_t evFork = 0, evJoin = 0;
    if (!s2) {
        cudaStreamCreateWithFlags(&s2, cudaStreamNonBlocking);
        cudaEventCreateWithFlags(&evFork, cudaEventDisableTiming);
        cudaEventCreateWithFlags(&evJoin, cudaEventDisableTiming);
    }

    k_split_zero<<<(F_IN * HID + 255) / 256, 256>>>(W1);       // launch 1 (main)

    cudaEventRecord(evFork, 0);
    cudaStreamWaitEvent(s2, evFork, 0);

    k_count<<<(E + 255) / 256, 256, 0, s2>>>(ei, E);           // launch 2 (s2)
    k_scan1<<<nb, 1024, 0, s2>>>(M);                           // launch 3 (s2)

    dim3 g1(HID / 128, (M + 127) / 128);
    k_gemm1<<<g1, 256>>>(features, M);                         // launch 4 (main) <- profiled

    k_scan2<<<1, 128, 0, s2>>>(nb);                            // launch 5 (s2)
    k_scan3<<<(M + 255) / 256, 256, 0, s2>>>(M, E);            // launch 6 (s2)
    k_bucket<<<(E + 255) / 256, 256, 0, s2>>>(ei, E);          // launch 7 (s2)

    cudaEventRecord(evJoin, s2);
    cudaStreamWaitEvent(0, evJoin, 0);

    k_agg1<<<M, 256>>>(M);                                     // launch 8
    k_gemm2<<<(M + 127) / 128, 256>>>(W2, b1, M);              // launch 9
    k_agg2soft<<<(M + 7) / 8, 256>>>(b2, out, M, write_soft);  // launch 10
}

// round 17
// speedup vs baseline: 1.4255x; 1.0300x over previous
#include <cuda_runtime.h>
#include <cuda_bf16.h>
#include <math.h>
#include <stdint.h>

#define F_IN 512
#define HID  256
#define NCLS 40
#define MAXN 100000
#define MAXE 1600000

// ---- scratch ----
__device__ float g_h1  [(size_t)MAXN * HID];
__device__ float g_agg1[(size_t)MAXN * HID];
__device__ float g_h2  [(size_t)MAXN * NCLS];
__device__ float g_dinv[MAXN];
__device__ int   g_cnt [MAXN];
__device__ int   g_rowstart[MAXN + 1];
__device__ int   g_cursor[MAXN];
__device__ int   g_se[MAXE];
__device__ float g_ce[MAXE];
__device__ int   g_bsum[128];
__device__ __nv_bfloat16 g_w1hi[(size_t)HID * F_IN];   // [n][k] transposed
__device__ __nv_bfloat16 g_w1lo[(size_t)HID * F_IN];

#define MMA_BF16(c, a, b) \
    asm volatile("mma.sync.aligned.m16n8k16.row.col.f32.bf16.bf16.f32 " \
                 "{%0,%1,%2,%3}, {%4,%5,%6,%7}, {%8,%9}, {%0,%1,%2,%3};" \
                 : "+f"((c)[0]), "+f"((c)[1]), "+f"((c)[2]), "+f"((c)[3]) \
                 : "r"((a)[0]), "r"((a)[1]), "r"((a)[2]), "r"((a)[3]), \
                   "r"((b)[0]), "r"((b)[1]))

#define LDSM4(r0, r1, r2, r3, addr) \
    asm volatile("ldmatrix.sync.aligned.m8n8.x4.shared.b16 {%0,%1,%2,%3}, [%4];" \
                 : "=r"(r0), "=r"(r1), "=r"(r2), "=r"(r3) : "r"(addr))

__device__ __forceinline__ uint32_t pack2(__nv_bfloat16 a, __nv_bfloat16 b) {
    return (uint32_t)__bfloat16_as_ushort(a) | ((uint32_t)__bfloat16_as_ushort(b) << 16);
}

__device__ __forceinline__ void cpa16(uint32_t dst_smem, const void* src, int src_size) {
    asm volatile("cp.async.ca.shared.global [%0], [%1], 16, %2;"
                 :: "r"(dst_smem), "l"(src), "r"(src_size));
}

// ---------------- prep ----------------
__global__ void k_split_zero(const float* __restrict__ W1) {
    int i = blockIdx.x * 256 + threadIdx.x;
    if (i < MAXN) g_cnt[i] = 0;
    if (i < F_IN * HID) {
        int k = i >> 8, n = i & 255;
        float w = W1[(size_t)k * HID + n];
        __nv_bfloat16 hi = __float2bfloat16_rn(w);
        __nv_bfloat16 lo = __float2bfloat16_rn(w - __bfloat162float(hi));
        g_w1hi[(size_t)n * F_IN + k] = hi;
        g_w1lo[(size_t)n * F_IN + k] = lo;
    }
}

__global__ void k_count(const int* __restrict__ ei, int E) {
    int e = blockIdx.x * 256 + threadIdx.x;
    if (e >= E) return;
    atomicAdd(&g_cnt[ei[E + e]], 1);
}

__global__ void k_scan1(int M) {
    __shared__ int sd[1024];
    int t = threadIdx.x, b = blockIdx.x;
    int i = b * 1024 + t;
    int v = (i < M) ? g_cnt[i] : 0;
    sd[t] = v;
    __syncthreads();
    for (int off = 1; off < 1024; off <<= 1) {
        int x = (t >= off) ? sd[t - off] : 0;
        __syncthreads();
        sd[t] += x;
        __syncthreads();
    }
    if (i < M) g_rowstart[i] = sd[t] - v;
    if (t == 1023) g_bsum[b] = sd[1023];
}

__global__ void k_scan2(int nb) {
    __shared__ int sd[128];
    int t = threadIdx.x;
    int v = (t < nb) ? g_bsum[t] : 0;
    sd[t] = v;
    __syncthreads();
    for (int off = 1; off < 128; off <<= 1) {
        int x = (t >= off) ? sd[t - off] : 0;
        __syncthreads();
        sd[t] += x;
        __syncthreads();
    }
    if (t < nb) g_bsum[t] = sd[t] - v;
}

__global__ void k_scan3(int M, int E) {
    int i = blockIdx.x * 256 + threadIdx.x;
    if (i >= M) return;
    int rs = g_rowstart[i] + g_bsum[i >> 10];
    g_rowstart[i] = rs;
    g_cursor[i] = rs;
    g_dinv[i] = rsqrtf((float)g_cnt[i] + 1.0f);
    if (i == 0) g_rowstart[M] = E;
}

__global__ void k_bucket(const int* __restrict__ ei, int E) {
    int e = blockIdx.x * 256 + threadIdx.x;
    if (e >= E) return;
    int s = ei[e], d = ei[E + e];
    int pos = atomicAdd(&g_cursor[d], 1);
    g_se[pos] = s;
    g_ce[pos] = g_dinv[s] * g_dinv[d];
}

// ---------------- GEMM1: cp.async pipelined bf16x3 + ldmatrix ----------------
// smem: Asm (converted bf16, packed rows [hi32|lo32], stride 72)
//       Bsm x2 (pre-split bf16, same packed layout)
//       Araw x2 (raw fp32, row stride 36 floats)
#define ASTR2 72
#define ARSTR 36
#define SM_ASM 0
#define SM_B0  18432
#define SM_B1  36864
#define SM_AR0 55296
#define SM_AR1 73728
#define SMEM1_TOTAL 92160

__global__ void __launch_bounds__(256, 2) k_gemm1(const float* __restrict__ A, int M) {
    extern __shared__ char sm[];
    __nv_bfloat16* Asm = (__nv_bfloat16*)(sm + SM_ASM);
    int tid = threadIdx.x, lane = tid & 31, wid = tid >> 5;
    int bm = blockIdx.y * 128, bn = blockIdx.x * 128;
    int m0 = (wid & 1) * 64, n0 = (wid >> 1) * 32;

    uint32_t smbase = (uint32_t)__cvta_generic_to_shared(sm);
    uint32_t aBase0 = smbase + SM_ASM +
                      (uint32_t)(((m0 + (lane & 15)) * ASTR2 + (lane >> 4) * 8) * 2);
    uint32_t bCommon = (uint32_t)(((n0 + (lane & 7)) * ASTR2 +
                                   ((lane >> 3) & 1) * 8 + (lane >> 4) * 32) * 2);

    float c[4][4][4];
#pragma unroll
    for (int i = 0; i < 4; i++)
#pragma unroll
        for (int j = 0; j < 4; j++)
#pragma unroll
            for (int r = 0; r < 4; r++) c[i][j][r] = 0.0f;

    // issue stage s into buffer b: 1024 (row m, chunk q) pairs; each thread does 4,
    // issuing one raw-A float4 and one B 16B chunk per pair.
#define ISSUE(b, s) do { \
        int k0_ = (s) * 32; \
        uint32_t arBase_ = smbase + ((b) ? SM_AR1 : SM_AR0); \
        uint32_t bBase_  = smbase + ((b) ? SM_B1  : SM_B0); \
        _Pragma("unroll") \
        for (int i_ = 0; i_ < 4; i_++) { \
            int ch_ = tid + i_ * 256; \
            int m_ = ch_ >> 3, q_ = ch_ & 7; \
            int asz_ = (bm + m_ < M) ? 16 : 0; \
            cpa16(arBase_ + (uint32_t)((m_ * ARSTR + q_ * 4) * 4), \
                  A + (size_t)(bm + m_) * F_IN + k0_ + q_ * 4, asz_); \
            if (q_ < 4) \
                cpa16(bBase_ + (uint32_t)((m_ * ASTR2 + q_ * 8) * 2), \
                      g_w1hi + (size_t)(bn + m_) * F_IN + k0_ + q_ * 8, 16); \
            else \
                cpa16(bBase_ + (uint32_t)((m_ * ASTR2 + 32 + (q_ - 4) * 8) * 2), \
                      g_w1lo + (size_t)(bn + m_) * F_IN + k0_ + (q_ - 4) * 8, 16); \
        } \
        asm volatile("cp.async.commit_group;"); \
    } while (0)

    // convert raw fp32 buffer b -> Asm (bf16 hi/lo packed)
#define CONVERT(b) do { \
        const char* ar_ = sm + ((b) ? SM_AR1 : SM_AR0); \
        _Pragma("unroll") \
        for (int i_ = 0; i_ < 4; i_++) { \
            int ch_ = tid + i_ * 256; \
            int m_ = ch_ >> 3, q_ = ch_ & 7; \
            float4 a_ = *(const float4*)(ar_ + (size_t)((m_ * ARSTR + q_ * 4) * 4)); \
            __nv_bfloat16 hx = __float2bfloat16_rn(a_.x), hy = __float2bfloat16_rn(a_.y); \
            __nv_bfloat16 hz = __float2bfloat16_rn(a_.z), hw = __float2bfloat16_rn(a_.w); \
            __nv_bfloat16 lx = __float2bfloat16_rn(a_.x - __bfloat162float(hx)); \
            __nv_bfloat16 ly = __float2bfloat16_rn(a_.y - __bfloat162float(hy)); \
            __nv_bfloat16 lz = __float2bfloat16_rn(a_.z - __bfloat162float(hz)); \
            __nv_bfloat16 lw = __float2bfloat16_rn(a_.w - __bfloat162float(hw)); \
            *(uint2*)&Asm[m_ * ASTR2 + q_ * 4]      = make_uint2(pack2(hx, hy), pack2(hz, hw)); \
            *(uint2*)&Asm[m_ * ASTR2 + 32 + q_ * 4] = make_uint2(pack2(lx, ly), pack2(lz, lw)); \
        } \
    } while (0)

    // prologue: stage 0
    ISSUE(0, 0);
    asm volatile("cp.async.wait_group 0;" ::: "memory");
    __syncthreads();
    CONVERT(0);
    __syncthreads();

    for (int s = 0; s < F_IN / 32; s++) {
        int cur = s & 1, nxt = cur ^ 1;
        if (s < F_IN / 32 - 1) ISSUE(nxt, s + 1);

        uint32_t bBase0 = smbase + (cur ? SM_B1 : SM_B0) + bCommon;
#pragma unroll
        for (int kk = 0; kk < 32; kk += 16) {
            uint32_t ah[4][4], al[4][4], bh[4][2], bl[4][2];
#pragma unroll
            for (int tm = 0; tm < 4; tm++) {
                uint32_t aa = aBase0 + (uint32_t)(tm * 16 * ASTR2 * 2 + kk * 2);
                LDSM4(ah[tm][0], ah[tm][1], ah[tm][2], ah[tm][3], aa);
                LDSM4(al[tm][0], al[tm][1], al[tm][2], al[tm][3], aa + 64);
            }
#pragma unroll
            for (int tn = 0; tn < 4; tn++) {
                uint32_t bb = bBase0 + (uint32_t)(tn * 8 * ASTR2 * 2 + kk * 2);
                LDSM4(bh[tn][0], bh[tn][1], bl[tn][0], bl[tn][1], bb);
            }
#pragma unroll
            for (int tm = 0; tm < 4; tm++)
#pragma unroll
                for (int tn = 0; tn < 4; tn++) {
                    MMA_BF16(c[tm][tn], ah[tm], bh[tn]);
                    MMA_BF16(c[tm][tn], ah[tm], bl[tn]);
                    MMA_BF16(c[tm][tn], al[tm], bh[tn]);
                }
        }

        if (s < F_IN / 32 - 1) {
            asm volatile("cp.async.wait_group 0;" ::: "memory");
            __syncthreads();           // all warps done with Asm + this stage's Bsm
            CONVERT(nxt);
            __syncthreads();           // Asm ready for next stage
        }
    }
#undef ISSUE
#undef CONVERT

#pragma unroll
    for (int tm = 0; tm < 4; tm++) {
        int row0 = bm + m0 + tm * 16 + (lane >> 2);
#pragma unroll
        for (int h = 0; h < 2; h++) {
            int row = row0 + h * 8;
            if (row >= M) continue;
#pragma unroll
            for (int tn = 0; tn < 4; tn++) {
                int col = bn + n0 + tn * 8 + (lane & 3) * 2;
                *(float2*)(g_h1 + (size_t)row * HID + col) =
                    make_float2(c[tm][tn][h * 2 + 0], c[tm][tn][h * 2 + 1]);
            }
        }
    }
}

// ---------------- agg layer 1: block per dst node, unroll 8, no atomics ----------------
__global__ void __launch_bounds__(256) k_agg1(int M) {
    int n = blockIdx.x;
    int tid = threadIdx.x;
    int st = g_rowstart[n], en = g_rowstart[n + 1];
    float dv = g_dinv[n];
    float acc = g_h1[(size_t)n * HID + tid] * (dv * dv);
    int e = st;
    for (; e + 7 < en; e += 8) {
        int   s[8];
        float cc[8], v[8];
#pragma unroll
        for (int q = 0; q < 8; q++) { s[q] = g_se[e + q]; cc[q] = g_ce[e + q]; }
#pragma unroll
        for (int q = 0; q < 8; q++) v[q] = __ldg(g_h1 + (size_t)s[q] * HID + tid);
#pragma unroll
        for (int q = 0; q < 8; q++) acc += v[q] * cc[q];
    }
    for (; e < en; e++)
        acc += __ldg(g_h1 + (size_t)g_se[e] * HID + tid) * g_ce[e];
    g_agg1[(size_t)n * HID + tid] = acc;
}

// ---------------- GEMM2 (bias+relu fused A-loader) ----------------
__global__ void __launch_bounds__(256) k_gemm2(const float* __restrict__ W2,
                                               const float* __restrict__ b1, int M) {
    __shared__ float As[32][128];
    __shared__ float Ws[32][NCLS];
    int tid = threadIdx.x;
    int tx = tid & 7, ty = tid >> 3;
    int bm = blockIdx.x * 128;

    float acc[4][5];
#pragma unroll
    for (int i = 0; i < 4; i++)
#pragma unroll
        for (int j = 0; j < 5; j++) acc[i][j] = 0.0f;

    for (int k0 = 0; k0 < HID; k0 += 32) {
#pragma unroll
        for (int i = 0; i < 4; i++) {
            int lin = tid + i * 256;
            int r = lin >> 3, c4 = lin & 7;
            int row = bm + r;
            float4 a4 = make_float4(0.f, 0.f, 0.f, 0.f);
            if (row < M) {
                a4 = *(const float4*)(g_agg1 + (size_t)row * HID + k0 + c4 * 4);
                float4 bb = *(const float4*)(b1 + k0 + c4 * 4);
                a4.x = fmaxf(a4.x + bb.x, 0.0f);
                a4.y = fmaxf(a4.y + bb.y, 0.0f);
                a4.z = fmaxf(a4.z + bb.z, 0.0f);
                a4.w = fmaxf(a4.w + bb.w, 0.0f);
            }
            As[c4 * 4 + 0][r] = a4.x;
            As[c4 * 4 + 1][r] = a4.y;
            As[c4 * 4 + 2][r] = a4.z;
            As[c4 * 4 + 3][r] = a4.w;
        }
#pragma unroll
        for (int i = 0; i < 5; i++) {
            int lin = tid + i * 256;
            int r = lin / NCLS, c = lin % NCLS;
            Ws[r][c] = W2[(size_t)(k0 + r) * NCLS + c];
        }
        __syncthreads();

#pragma unroll
        for (int kk = 0; kk < 32; kk++) {
            float4 a = *(float4*)&As[kk][ty * 4];
            float av[4] = {a.x, a.y, a.z, a.w};
            float w[5];
#pragma unroll
            for (int j = 0; j < 5; j++) w[j] = Ws[kk][tx * 5 + j];
#pragma unroll
            for (int i = 0; i < 4; i++)
#pragma unroll
                for (int j = 0; j < 5; j++)
                    acc[i][j] = fmaf(av[i], w[j], acc[i][j]);
        }
        __syncthreads();
    }

#pragma unroll
    for (int i = 0; i < 4; i++) {
        int row = bm + ty * 4 + i;
        if (row >= M) continue;
#pragma unroll
        for (int j = 0; j < 5; j++)
            g_h2[(size_t)row * NCLS + tx * 5 + j] = acc[i][j];
    }
}

// ---------------- fused agg layer 2 + bias + log_softmax/softmax ----------------
__global__ void __launch_bounds__(256) k_agg2soft(const float* __restrict__ b2,
                                                  float* __restrict__ out,
                                                  int M, int write_soft) {
    int warp = threadIdx.x >> 5, lane = threadIdx.x & 31;
    int n = blockIdx.x * 8 + warp;
    if (n >= M) return;
    int st = g_rowstart[n], en = g_rowstart[n + 1];
    float dv = g_dinv[n];
    float d2 = dv * dv;
    bool has1 = lane < (NCLS - 32);
    const float* hn = g_h2 + (size_t)n * NCLS;
    float a0 = hn[lane] * d2;
    float a1 = has1 ? hn[32 + lane] * d2 : 0.0f;
    for (int e = st; e < en; e++) {
        int s = g_se[e];
        float cc = g_ce[e];
        const float* hs = g_h2 + (size_t)s * NCLS;
        a0 += hs[lane] * cc;
        if (has1) a1 += hs[32 + lane] * cc;
    }
    float v0 = a0 + b2[lane];
    float v1 = has1 ? (a1 + b2[32 + lane]) : -INFINITY;
    float m = fmaxf(v0, v1);
#pragma unroll
    for (int o = 16; o; o >>= 1) m = fmaxf(m, __shfl_xor_sync(0xffffffffu, m, o));
    float s = expf(v0 - m) + (has1 ? expf(v1 - m) : 0.0f);
#pragma unroll
    for (int o = 16; o; o >>= 1) s += __shfl_xor_sync(0xffffffffu, s, o);
    float lse = m + logf(s);
    float l0 = v0 - lse;
    out[(size_t)n * NCLS + lane] = l0;
    if (write_soft) out[(size_t)M * NCLS + (size_t)n * NCLS + lane] = expf(l0);
    if (has1) {
        float l1 = v1 - lse;
        out[(size_t)n * NCLS + lane + 32] = l1;
        if (write_soft) out[(size_t)M * NCLS + (size_t)n * NCLS + lane + 32] = expf(l1);
    }
}

extern "C" void kernel_launch(void* const* d_in, const int* in_sizes, int n_in,
                              void* d_out, int out_size) {
    const float* features = (const float*)d_in[0];
    const float* W1       = (const float*)d_in[1];
    const float* b1       = (const float*)d_in[2];
    const float* W2       = (const float*)d_in[3];
    const float* b2       = (const float*)d_in[4];
    const int*   ei       = (const int*)d_in[5];

    int M = in_sizes[0] / F_IN;
    int E = in_sizes[5] / 2;
    float* out = (float*)d_out;
    int write_soft = (out_size >= 2 * M * NCLS) ? 1 : 0;
    int nb = (M + 1023) / 1024;

    static cudaStream_t s2 = 0;
    static cudaEvent_t evFork = 0, evJoin = 0;
    if (!s2) {
        cudaStreamCreateWithFlags(&s2, cudaStreamNonBlocking);
        cudaEventCreateWithFlags(&evFork, cudaEventDisableTiming);
        cudaEventCreateWithFlags(&evJoin, cudaEventDisableTiming);
        cudaFuncSetAttribute(k_gemm1, cudaFuncAttributeMaxDynamicSharedMemorySize, SMEM1_TOTAL);
    }

    k_split_zero<<<(F_IN * HID + 255) / 256, 256>>>(W1);       // launch 1 (main)

    cudaEventRecord(evFork, 0);
    cudaStreamWaitEvent(s2, evFork, 0);

    k_count<<<(E + 255) / 256, 256, 0, s2>>>(ei, E);           // launch 2 (s2)
    k_scan1<<<nb, 1024, 0, s2>>>(M);                           // launch 3 (s2)

    dim3 g1(HID / 128, (M + 127) / 128);
    k_gemm1<<<g1, 256, SMEM1_TOTAL>>>(features, M);            // launch 4 (main) <- profiled

    k_scan2<<<1, 128, 0, s2>>>(nb);                            // launch 5 (s2)
    k_scan3<<<(M + 255) / 256, 256, 0, s2>>>(M, E);            // launch 6 (s2)
    k_bucket<<<(E + 255) / 256, 256, 0, s2>>>(ei, E);          // launch 7 (s2)

    cudaEventRecord(evJoin, s2);
    cudaStreamWaitEvent(0, evJoin, 0);

    k_agg1<<<M, 256>>>(M);                                     // launch 8
    k_gemm2<<<(M + 127) / 128, 256>>>(W2, b1, M);              // launch 9
    k_agg2soft<<<(M + 7) / 8, 256>>>(b2, out, M, write_soft);  // launch 10
}